// round 10
// baseline (speedup 1.0000x reference)
#include <cuda_runtime.h>
#include <cstdint>
#include <cstddef>

// B=4, H=8, N=256, D=32
//   scores[b,h,i,j,d] = q[b,h,i,d]*k[b,h,j,d]*edges[b,h,i,j,d]
//   logits = sum_d(scores)/sqrt(D) + mask[b,i,j]; attn = softmax_j
//   out[b,i,h*D+d]        = sum_j attn*v[b,h,j,d]
//   edge_out[b,j,i,h*D+d] = scores
// d_out = [ out (262144) | edge_out (67108864) ]
//
// v9 = v8 (CTA = (b, i-pair) x 8 heads, warp = head, per-warp bulk-copy into
// shared 3x32KB ring, online no-max softmax, warp-local epilogue) made
// PERSISTENT: grid 256 (single wave), each CTA runs 2 consecutive i-pair
// tasks with a flattened 32-chunk loop whose refills cross the task
// boundary -> no pipeline drain between tasks, no wave-2 tail.

#define FULLM 0xffffffffu
#define JC        16                       // j per chunk
#define DEPTH     3
#define NCHUNK    16                       // chunks per task
#define NTASK     2
#define TOTCHUNK  (NCHUNK * NTASK)         // 32
#define SLOT_FLOATS (8 * 2 * JC * 32)      // 8192 floats = 32KB
#define SECT_FLOATS (2 * JC * 32)          // per-warp section: 1024
#define HALF_FLOATS (JC * 32)              // per (h,i): 512 floats = 2KB

__device__ __forceinline__ uint32_t s2u(const void* p) {
    uint32_t a;
    asm("{ .reg .u64 t; cvta.to.shared.u64 t, %1; cvt.u32.u64 %0, t; }"
        : "=r"(a) : "l"(p));
    return a;
}
__device__ __forceinline__ void mbar_init(uint32_t a, uint32_t cnt) {
    asm volatile("mbarrier.init.shared.b64 [%0], %1;" :: "r"(a), "r"(cnt) : "memory");
}
__device__ __forceinline__ void mbar_expect_tx(uint32_t a, uint32_t bytes) {
    asm volatile("mbarrier.arrive.expect_tx.shared.b64 _, [%0], %1;"
                 :: "r"(a), "r"(bytes) : "memory");
}
__device__ __forceinline__ void bulk_g2s(uint32_t dst, const void* src,
                                         uint32_t bytes, uint32_t mbar) {
    asm volatile(
        "cp.async.bulk.shared::cta.global.mbarrier::complete_tx::bytes "
        "[%0], [%1], %2, [%3];"
        :: "r"(dst), "l"(src), "r"(bytes), "r"(mbar) : "memory");
}
__device__ __forceinline__ void mbar_wait(uint32_t a, uint32_t parity) {
    asm volatile(
        "{\n\t.reg .pred P;\n\t"
        "WL_%=:\n\t"
        "mbarrier.try_wait.parity.shared.b64 P, [%0], %1, 0x989680;\n\t"
        "@P bra.uni WD_%=;\n\t"
        "bra.uni WL_%=;\n\t"
        "WD_%=:\n\t}"
        :: "r"(a), "r"(parity) : "memory");
}

__global__ __launch_bounds__(256, 2)
void edge_attn_v9(const float* __restrict__ q,
                  const float* __restrict__ k,
                  const float* __restrict__ v,
                  const float* __restrict__ e,
                  const float* __restrict__ mask,
                  float* __restrict__ out,
                  float* __restrict__ eout)
{
    extern __shared__ float dsm[];           // DEPTH * 32KB = 96KB
    __shared__ uint64_t mbar[DEPTH];

    const int tid  = threadIdx.x;
    const int w    = tid >> 5;     // warp = head h
    const int lane = tid & 31;
    const int o    = lane >> 3;    // octet: j within 4-group
    const int cc   = lane & 7;     // d-chunk (4 floats)

    // CTA owns tasks t0 = 2*cta, t0+1.  task t: b = t>>7, i0 = (t&127)*2.
    const int cta = blockIdx.x;    // 0..255
    const int t0  = cta * 2;
    const int b   = t0 >> 7;       // both tasks share b
    const int bh  = b * 8 + w;

    const float4* __restrict__ kb4 = (const float4*)(k + (size_t)bh * 8192) + cc;
    const float4* __restrict__ vb4 = (const float4*)(v + (size_t)bh * 8192) + cc;
    // edges base for this (b,h), indexed by absolute i
    const float*  __restrict__ ebh = e + (size_t)bh * 256 * 8192;

    uint32_t mb[DEPTH];
    #pragma unroll
    for (int s = 0; s < DEPTH; ++s) mb[s] = s2u(&mbar[s]);
    const uint32_t dsm_u = s2u(dsm);
    const uint32_t sect0 = dsm_u + (uint32_t)(w * SECT_FLOATS) * 4;

    if (tid == 0) {
        #pragma unroll
        for (int s = 0; s < DEPTH; ++s) mbar_init(mb[s], 8);
        asm volatile("fence.proxy.async.shared::cta;" ::: "memory");
    }
    __syncthreads();   // the ONLY CTA barrier

    // refill helper logic (inlined): global chunk gc -> task t0 + (gc>>4),
    // local chunk gc&15, i0 = ((task)&127)*2
    // prologue: chunks 0..DEPTH-1 (all within task 0 since NCHUNK=16>3)
    if (lane == 0) {
        const int i0p = (t0 & 127) * 2;
        const float* es0 = ebh + (size_t)i0p * 8192;
        #pragma unroll
        for (int s = 0; s < DEPTH; ++s) {
            const uint32_t base = sect0 + (uint32_t)(s * SLOT_FLOATS) * 4;
            mbar_expect_tx(mb[s], 2 * HALF_FLOATS * 4);
            bulk_g2s(base,                   es0 + s * HALF_FLOATS,        HALF_FLOATS * 4, mb[s]);
            bulk_g2s(base + HALF_FLOATS * 4, es0 + 8192 + s * HALF_FLOATS, HALF_FLOATS * 4, mb[s]);
        }
    }

    const float SCALE = 0.17677669529663687f;  // 1/sqrt(32)

    int slot = 0, parity = 0;

    for (int task = 0; task < NTASK; ++task) {
        const int t  = t0 + task;
        const int i0 = (t & 127) * 2;

        const float4 qv0 = *(const float4*)(q + ((size_t)bh * 256 + i0    ) * 32 + cc * 4);
        const float4 qv1 = *(const float4*)(q + ((size_t)bh * 256 + i0 + 1) * 32 + cc * 4);
        const float* __restrict__ mr0 = mask + ((size_t)b * 256 + i0) * 256;
        const float* __restrict__ mr1 = mr0 + 256;
        float4* __restrict__ eo0 = (float4*)eout
            + (size_t)b * 4194304 + (size_t)i0 * 64 + w * 8 + cc;
        float4* __restrict__ eo1 = eo0 + 64;

        float4 acc0 = make_float4(0.f, 0.f, 0.f, 0.f);
        float4 acc1 = make_float4(0.f, 0.f, 0.f, 0.f);
        float  ss0 = 0.f, ss1 = 0.f;

        for (int c = 0; c < NCHUNK; ++c) {
            mbar_wait(mb[slot], parity);

            const float* __restrict__ buf0 = dsm + slot * SLOT_FLOATS + w * SECT_FLOATS;
            const float* __restrict__ buf1 = buf0 + HALF_FLOATS;

            #pragma unroll
            for (int g = 0; g < 4; ++g) {
                const int jl = g * 4 + o;       // 0..15
                const int j  = c * JC + jl;
                float4 k4 = __ldg(kb4 + (size_t)j * 8);
                float4 v4 = __ldg(vb4 + (size_t)j * 8);
                float4 e0 = *(const float4*)(buf0 + jl * 32 + cc * 4);
                float4 e1 = *(const float4*)(buf1 + jl * 32 + cc * 4);

                float4 s0, s1;
                s0.x = qv0.x * k4.x * e0.x;  s1.x = qv1.x * k4.x * e1.x;
                s0.y = qv0.y * k4.y * e0.y;  s1.y = qv1.y * k4.y * e1.y;
                s0.z = qv0.z * k4.z * e0.z;  s1.z = qv1.z * k4.z * e1.z;
                s0.w = qv0.w * k4.w * e0.w;  s1.w = qv1.w * k4.w * e1.w;
                eo0[(size_t)j * 16384] = s0;
                eo1[(size_t)j * 16384] = s1;

                float ts0 = (s0.x + s0.y) + (s0.z + s0.w);
                float ts1 = (s1.x + s1.y) + (s1.z + s1.w);
                ts0 += __shfl_xor_sync(FULLM, ts0, 1);
                ts1 += __shfl_xor_sync(FULLM, ts1, 1);
                ts0 += __shfl_xor_sync(FULLM, ts0, 2);
                ts1 += __shfl_xor_sync(FULLM, ts1, 2);
                ts0 += __shfl_xor_sync(FULLM, ts0, 4);
                ts1 += __shfl_xor_sync(FULLM, ts1, 4);

                float p0 = __expf(ts0 * SCALE + __ldg(mr0 + j));  // no-max softmax
                float p1 = __expf(ts1 * SCALE + __ldg(mr1 + j));
                ss0 += p0;  ss1 += p1;
                acc0.x = fmaf(p0, v4.x, acc0.x);  acc1.x = fmaf(p1, v4.x, acc1.x);
                acc0.y = fmaf(p0, v4.y, acc0.y);  acc1.y = fmaf(p1, v4.y, acc1.y);
                acc0.z = fmaf(p0, v4.z, acc0.z);  acc1.z = fmaf(p1, v4.z, acc1.z);
                acc0.w = fmaf(p0, v4.w, acc0.w);  acc1.w = fmaf(p1, v4.w, acc1.w);
            }

            __syncwarp();   // warp done reading its section
            const int gc = task * NCHUNK + c;
            if (lane == 0 && gc + DEPTH < TOTCHUNK) {
                const int ngc  = gc + DEPTH;
                const int nt   = t0 + (ngc >> 4);
                const int nc   = ngc & 15;
                const int ni0  = (nt & 127) * 2;
                const float* nes0 = ebh + (size_t)ni0 * 8192;
                const uint32_t base = sect0 + (uint32_t)(slot * SLOT_FLOATS) * 4;
                mbar_expect_tx(mb[slot], 2 * HALF_FLOATS * 4);
                bulk_g2s(base,                   nes0 + nc * HALF_FLOATS,        HALF_FLOATS * 4, mb[slot]);
                bulk_g2s(base + HALF_FLOATS * 4, nes0 + 8192 + nc * HALF_FLOATS, HALF_FLOATS * 4, mb[slot]);
            }
            if (++slot == DEPTH) { slot = 0; parity ^= 1; }
        }

        // warp-local epilogue: combine the 4 octets (j mod 4 partitions)
        #pragma unroll
        for (int off = 8; off <= 16; off <<= 1) {
            acc0.x += __shfl_xor_sync(FULLM, acc0.x, off);
            acc0.y += __shfl_xor_sync(FULLM, acc0.y, off);
            acc0.z += __shfl_xor_sync(FULLM, acc0.z, off);
            acc0.w += __shfl_xor_sync(FULLM, acc0.w, off);
            ss0    += __shfl_xor_sync(FULLM, ss0,    off);
            acc1.x += __shfl_xor_sync(FULLM, acc1.x, off);
            acc1.y += __shfl_xor_sync(FULLM, acc1.y, off);
            acc1.z += __shfl_xor_sync(FULLM, acc1.z, off);
            acc1.w += __shfl_xor_sync(FULLM, acc1.w, off);
            ss1    += __shfl_xor_sync(FULLM, ss1,    off);
        }
        if (o == 0) {
            const float r0 = 1.0f / ss0, r1 = 1.0f / ss1;
            float4 o0 = make_float4(acc0.x * r0, acc0.y * r0, acc0.z * r0, acc0.w * r0);
            float4 o1 = make_float4(acc1.x * r1, acc1.y * r1, acc1.z * r1, acc1.w * r1);
            float* obase = out + ((size_t)b * 256 + i0) * 256 + w * 32 + cc * 4;
            *(float4*)obase         = o0;
            *(float4*)(obase + 256) = o1;
        }
    }
}

extern "C" void kernel_launch(void* const* d_in, const int* in_sizes, int n_in,
                              void* d_out, int out_size)
{
    const float* q    = (const float*)d_in[0];
    const float* k    = (const float*)d_in[1];
    const float* v    = (const float*)d_in[2];
    const float* e    = (const float*)d_in[3];
    const float* mask = (const float*)d_in[4];
    float* out  = (float*)d_out;
    float* eout = out + (size_t)4 * 256 * 256;  // 262144

    const int dyn_smem = DEPTH * SLOT_FLOATS * 4;   // 96KB
    cudaFuncSetAttribute(edge_attn_v9,
                         cudaFuncAttributeMaxDynamicSharedMemorySize, dyn_smem);
    edge_attn_v9<<<256, 256, dyn_smem>>>(q, k, v, e, mask, out, eout);
}